// round 16
// baseline (speedup 1.0000x reference)
#include <cuda_runtime.h>

#define BB 16
#define NN 16384
#define GG 128
#define NS 256
#define NFG 64
#define CAP 2048

typedef unsigned long long ull;

// Scratch (no allocations allowed).
__device__ __align__(16) unsigned g_packed[BB*NN];  // (m << 2) | labcode (1=pos,2=neg,0=neu)
__device__ int g_hist[BB*3*2048];                   // [b][cat][2048]; zeroed by stage2

// ---------------------------------------------------------------------------
// Packed f32x2 helpers (sm_100+: only add/sub/mul/fma exist)
// ---------------------------------------------------------------------------
__device__ __forceinline__ ull pack2(float lo, float hi) {
  ull r; asm("mov.b64 %0, {%1, %2};" : "=l"(r) : "f"(lo), "f"(hi)); return r;
}
__device__ __forceinline__ void unpack2(ull v, float& lo, float& hi) {
  asm("mov.b64 {%0, %1}, %2;" : "=f"(lo), "=f"(hi) : "l"(v));
}
__device__ __forceinline__ ull add2(ull a, ull b) {
  ull r; asm("add.rn.f32x2 %0, %1, %2;" : "=l"(r) : "l"(a), "l"(b)); return r;
}
__device__ __forceinline__ ull sub2(ull a, ull b) {
  ull r; asm("sub.rn.f32x2 %0, %1, %2;" : "=l"(r) : "l"(a), "l"(b)); return r;
}
__device__ __forceinline__ ull mul2(ull a, ull b) {
  ull r; asm("mul.rn.f32x2 %0, %1, %2;" : "=l"(r) : "l"(a), "l"(b)); return r;
}
__device__ __forceinline__ ull fma2(ull a, ull b, ull c) {
  ull r; asm("fma.rn.f32x2 %0, %1, %2, %3;" : "=l"(r) : "l"(a), "l"(b), "l"(c)); return r;
}
// per-lane abs + exact clamp: x + |x| = 2*max(x,0) exactly
__device__ __forceinline__ ull clamp2x(ull x) {
  return add2(x, x & 0x7FFFFFFF7FFFFFFFull);
}

// ---------------------------------------------------------------------------
// JAX threefry2x32, key = jax.random.key(1) -> (0,1); partitionable path.
// ---------------------------------------------------------------------------
__device__ __forceinline__ uint2 threefry2x32(unsigned x0, unsigned x1) {
  const unsigned ks0 = 0u, ks1 = 1u, ks2 = 0x1BD11BDBu;
  unsigned ks[3] = {ks0, ks1, ks2};
  x0 += ks[0]; x1 += ks[1];
  const int R0[4] = {13, 15, 26, 6};
  const int R1[4] = {17, 29, 16, 24};
#pragma unroll
  for (int i = 0; i < 5; ++i) {
#pragma unroll
    for (int j = 0; j < 4; ++j) {
      int r = (i & 1) ? R1[j] : R0[j];
      x0 += x1;
      x1 = (x1 << r) | (x1 >> (32 - r));
      x1 ^= x0;
    }
    x0 += ks[(i + 1) % 3];
    x1 += ks[(i + 2) % 3] + (unsigned)(i + 1);
  }
  return make_uint2(x0, x1);
}
__device__ __forceinline__ unsigned jax_bits(unsigned i) {
  uint2 o = threefry2x32(0u, i);
  return o.x ^ o.y;
}

// Correctly-rounded fp32 divide, fast path only. Bit-identical to __fdiv_rn
// for the normal/no-overflow operand ranges in this problem.
__device__ __forceinline__ float fdiv_rn_fast(float a, float b) {
  float y;
  asm("rcp.approx.f32 %0, %1;" : "=f"(y) : "f"(b));
  float e = __fmaf_rn(-b, y, 1.0f);
  y = __fmaf_rn(e, y, y);
  float q = __fmul_rn(a, y);
  float r = __fmaf_rn(-b, q, a);
  return __fmaf_rn(r, y, q);
}

__device__ __forceinline__ float iou_one(float4 p, float ap, float4 q, float ag) {
  float ix1 = fmaxf(p.x, q.x), iy1 = fmaxf(p.y, q.y);
  float ix2 = fminf(p.z, q.z), iy2 = fminf(p.w, q.w);
  float iw = fmaxf(__fsub_rn(ix2, ix1), 0.0f);
  float ih = fmaxf(__fsub_rn(iy2, iy1), 0.0f);
  float inter = __fmul_rn(iw, ih);
  float den = __fsub_rn(__fadd_rn(ap, ag), inter);   // max(.,1e-8) clamp no-op
  return fdiv_rn_fast(inter, den);
}

// ---------------------------------------------------------------------------
// Stage 1: approx threshold scores via packed f32x2 + exact repair in a
// two-sided danger band. Lane lo = proposal n0, hi = proposal n0+256.
//   s1 ~ 1.5*inter - 0.5*(ap+ag)   (>=0 -> iou >= 0.5)
//   s2 ~ 1.1*inter - 0.1*(ap+ag)   (>=0 -> iou >= 0.1)
// inter4 = 4*inter EXACT (clamp trick), so s1 = fma(inter4, 0.375, c1).
// ---------------------------------------------------------------------------
__global__ void ptl_stage1(const float* __restrict__ prop, const float* __restrict__ gt) {
  __shared__ float4 sgt[GG];
  __shared__ float  sag[GG];
  __shared__ ull scg1[GG], scg2[GG];   // packed (-0.5*ag, -0.5*ag), (-0.1*ag, ...)
  const int b = blockIdx.y;
  const int tid = threadIdx.x;
  const int n0 = blockIdx.x * 512 + tid;
  if (tid < GG) {
    float4 q = reinterpret_cast<const float4*>(gt)[b * GG + tid];
    float ag = __fmul_rn(__fsub_rn(q.z, q.x), __fsub_rn(q.w, q.y));
    sgt[tid] = q; sag[tid] = ag;
    float c1 = __fmul_rn(-0.5f, ag);    // exact
    float c2 = __fmul_rn(-0.1f, ag);
    scg1[tid] = pack2(c1, c1);
    scg2[tid] = pack2(c2, c2);
  }
  __syncthreads();

  float4 pA = reinterpret_cast<const float4*>(prop)[b * NN + n0];
  float4 pB = reinterpret_cast<const float4*>(prop)[b * NN + n0 + 256];
  float apA = __fmul_rn(__fsub_rn(pA.z, pA.x), __fsub_rn(pA.w, pA.y));
  float apB = __fmul_rn(__fsub_rn(pB.z, pB.x), __fsub_rn(pB.w, pB.y));

  const ull cp1 = pack2(__fmul_rn(-0.5f, apA), __fmul_rn(-0.5f, apB));
  const ull cp2 = pack2(__fmul_rn(-0.1f, apA), __fmul_rn(-0.1f, apB));
  const ull k0375 = pack2(0.375f, 0.375f);   // 1.5/4
  const ull k0275 = pack2(0.275f, 0.275f);   // 1.1/4
  float s1A = -3.4e38f, s1B = -3.4e38f, s2A = -3.4e38f, s2B = -3.4e38f;

#pragma unroll 4
  for (int g = 0; g < GG; ++g) {
    float4 q = sgt[g];
    // scalar coord min/max (no packed min/max on sm_103a)
    float ix1A = fmaxf(pA.x, q.x), iy1A = fmaxf(pA.y, q.y);
    float ix2A = fminf(pA.z, q.z), iy2A = fminf(pA.w, q.w);
    float ix1B = fmaxf(pB.x, q.x), iy1B = fmaxf(pB.y, q.y);
    float ix2B = fminf(pB.z, q.z), iy2B = fminf(pB.w, q.w);
    ull iw = sub2(pack2(ix2A, ix2B), pack2(ix1A, ix1B));
    ull ih = sub2(pack2(iy2A, iy2B), pack2(iy1A, iy1B));
    ull inter4 = mul2(clamp2x(iw), clamp2x(ih));     // exactly 4*inter
    ull c1 = add2(cp1, scg1[g]);
    ull c2 = add2(cp2, scg2[g]);
    ull s1 = fma2(inter4, k0375, c1);
    ull s2 = fma2(inter4, k0275, c2);
    float s1l, s1h, s2l, s2h;
    unpack2(s1, s1l, s1h);
    unpack2(s2, s2l, s2h);
    s1A = fmaxf(s1A, s1l); s1B = fmaxf(s1B, s1h);
    s2A = fmaxf(s2A, s2l); s2B = fmaxf(s2B, s2h);
  }

#pragma unroll
  for (int e = 0; e < 2; ++e) {
    float s1 = e ? s1B : s1A, s2 = e ? s2B : s2A;
    float4 p = e ? pB : pA;
    float ap = e ? apB : apA;
    int n = n0 + e * 256;
    int lc;
    // two-sided danger band (approx scores) -> exact repair
    bool danger = (fabsf(s1) < 0.02f) || (fabsf(s2) < 0.01f);
    if (danger) {
      float best = 0.0f;
      for (int g = 0; g < GG; ++g)
        best = fmaxf(best, iou_one(p, ap, sgt[g], sag[g]));
      lc = (best >= 0.5f) ? 1 : ((best < 0.1f) ? 2 : 0);
    } else {
      lc = (s1 >= 0.0f) ? 1 : ((s2 < 0.0f) ? 2 : 0);
    }
    int i = b * NN + n;
    unsigned m = jax_bits((unsigned)i) >> 9;   // r = m * 2^-23 exactly
    g_packed[i] = (m << 2) | (unsigned)lc;
    atomicAdd(&g_hist[(b * 3 + lc) * 2048 + (int)(m >> 12)], 1);
  }
}

// ---------------------------------------------------------------------------
// Stage 2 helpers
// ---------------------------------------------------------------------------
__device__ __forceinline__ int3 blockSuffixScan3(int3 v, int3* wsum) {
  const int lane = threadIdx.x & 31, w = threadIdx.x >> 5;
  int a = v.x, b2 = v.y, c = v.z;
#pragma unroll
  for (int o = 1; o < 32; o <<= 1) {
    int xa = __shfl_down_sync(0xffffffffu, a, o);
    int xb = __shfl_down_sync(0xffffffffu, b2, o);
    int xc = __shfl_down_sync(0xffffffffu, c, o);
    if (lane + o < 32) { a += xa; b2 += xb; c += xc; }
  }
  if (lane == 0) wsum[w] = make_int3(a, b2, c);
  __syncthreads();
  if (threadIdx.x < 32) {
    int3 t = wsum[threadIdx.x];
    int ta = t.x, tb = t.y, tc = t.z;
#pragma unroll
    for (int o = 1; o < 32; o <<= 1) {
      int xa = __shfl_down_sync(0xffffffffu, ta, o);
      int xb = __shfl_down_sync(0xffffffffu, tb, o);
      int xc = __shfl_down_sync(0xffffffffu, tc, o);
      if (threadIdx.x + o < 32) { ta += xa; tb += xb; tc += xc; }
    }
    wsum[threadIdx.x] = make_int3(ta - t.x, tb - t.y, tc - t.z);
  }
  __syncthreads();
  int3 r = wsum[w];
  return make_int3(a + r.x, b2 + r.y, c + r.z);
}

__device__ __forceinline__ void markCut(int suf, int h0, int h1, int T, int* dst) {
  int s0 = suf, s1 = suf - h0, s2 = s1 - h1;
  if (s0 >= T && s1 < T) *dst = 2 * (int)threadIdx.x;
  if (s1 >= T && s2 < T) *dst = 2 * (int)threadIdx.x + 1;
}

__device__ __forceinline__ int countGreater8(const ull* arr, int len8, ull k) {
  int rk = 0;
  for (int j = 0; j < len8; j += 8) {
    ull a0 = arr[j], a1 = arr[j+1], a2 = arr[j+2], a3 = arr[j+3];
    ull a4 = arr[j+4], a5 = arr[j+5], a6 = arr[j+6], a7 = arr[j+7];
    rk += (int)(a0 > k) + (int)(a1 > k) + (int)(a2 > k) + (int)(a3 > k)
        + (int)(a4 > k) + (int)(a5 > k) + (int)(a6 > k) + (int)(a7 > k);
  }
  return rk;
}

// warp-exclusive prefix + one atomic per warp; returns this thread's base offset
__device__ __forceinline__ int warpAppendBase(int cnt, int* counter) {
  const int lane = threadIdx.x & 31;
  int inc = cnt;
#pragma unroll
  for (int o = 1; o < 32; o <<= 1) {
    int y = __shfl_up_sync(0xffffffffu, inc, o);
    if (lane >= o) inc += y;
  }
  int base;
  if (lane == 31) base = atomicAdd(counter, inc);   // inc@31 == warp total
  base = __shfl_sync(0xffffffffu, base, 31);
  return base + inc - cnt;
}

// ---------------------------------------------------------------------------
// Stage 2: one CTA/batch. Histogram cuts -> gather -> exact ranking.
// ---------------------------------------------------------------------------
__global__ void __launch_bounds__(1024) ptl_stage2(const float* __restrict__ prop,
                                                   const float* __restrict__ gt,
                                                   float* __restrict__ out) {
  __shared__ int3 wsum[32];
  __shared__ int s_binP, s_binN, s_binU, s_cnt, s_pcnt;
  __shared__ int3 s_tot;
  __shared__ float4 sgt[GG];
  __shared__ float  sag[GG];
  __shared__ ull candArr[CAP];
  __shared__ ull posArr[CAP];
  __shared__ ull skey[CAP];

  const int b = blockIdx.x;
  const int tid = threadIdx.x;

  // Prefetch packed data early (hidden under histogram phase).
  uint4 pk[4];
  const uint4* gp = reinterpret_cast<const uint4*>(&g_packed[b * NN]);
#pragma unroll
  for (int j = 0; j < 4; ++j) pk[j] = __ldg(&gp[tid + j * 1024]);

  if (tid < GG) {
    float4 q = reinterpret_cast<const float4*>(gt)[b * GG + tid];
    sgt[tid] = q;
    sag[tid] = __fmul_rn(__fsub_rn(q.z, q.x), __fsub_rn(q.w, q.y));
  }

  // Per-batch histograms (thread t owns bins 2t,2t+1); zero for next replay.
  int2* hb = reinterpret_cast<int2*>(&g_hist[b * 3 * 2048]);
  int2 hU = hb[0 * 1024 + tid];
  int2 hP = hb[1 * 1024 + tid];
  int2 hN = hb[2 * 1024 + tid];
  hb[0 * 1024 + tid] = make_int2(0, 0);
  hb[1 * 1024 + tid] = make_int2(0, 0);
  hb[2 * 1024 + tid] = make_int2(0, 0);

  if (tid == 0) { s_cnt = 0; s_pcnt = 0; s_binP = 0; s_binN = 0; s_binU = 2048; }
  __syncthreads();

  int3 suf = blockSuffixScan3(make_int3(hP.x + hP.y, hN.x + hN.y, hU.x + hU.y), wsum);
  if (tid == 0) s_tot = suf;
  __syncthreads();
  const int npos = s_tot.x, nneg = s_tot.y;
  const int S1 = (npos < NFG) ? npos : NFG;
  const int T2 = NS - S1;
  const bool fallback = (nneg < T2);
  const int TU = T2 - nneg - ((npos > NFG) ? (npos - NFG) : 0);

  if (npos > NFG && !fallback) markCut(suf.x, hP.x, hP.y, NFG, &s_binP);
  if (!fallback)               markCut(suf.y, hN.x, hN.y, T2,  &s_binN);
  else if (TU >= 1)            markCut(suf.z, hU.x, hU.y, TU,  &s_binU);
  __syncthreads();

  const unsigned mA = (npos > NFG && !fallback) ? ((unsigned)s_binP << 12) : 0u;
  const unsigned mB = fallback ? 0u : ((unsigned)s_binN << 12);
  const unsigned mU = (unsigned)s_binU << 12;
  const bool needPosRank = (npos > NFG);

  // ---- gather: per-thread 16-bit masks, one warp scan + one atomic/warp ----
  unsigned candMask = 0, posMask = 0;
#pragma unroll
  for (int j = 0; j < 4; ++j) {
    unsigned vals[4] = {pk[j].x, pk[j].y, pk[j].z, pk[j].w};
#pragma unroll
    for (int e = 0; e < 4; ++e) {
      unsigned v = vals[e];
      unsigned lc = v & 3u;
      unsigned m = v >> 2;
      bool c = (lc == 1u) ? (m >= mA) : (lc == 2u) ? (m >= mB) : (m >= mU);
      candMask |= (unsigned)c << (j * 4 + e);
      posMask |= (unsigned)(c && lc == 1u) << (j * 4 + e);
    }
  }
  int off = warpAppendBase(__popc(candMask), &s_cnt);
  int poff = needPosRank ? warpAppendBase(__popc(posMask), &s_pcnt) : 0;
#pragma unroll
  for (int j = 0; j < 4; ++j) {
    unsigned vals[4] = {pk[j].x, pk[j].y, pk[j].z, pk[j].w};
#pragma unroll
    for (int e = 0; e < 4; ++e) {
      int bit = j * 4 + e;
      if ((candMask >> bit) & 1u) {
        unsigned v = vals[e];
        unsigned lc = v & 3u;
        unsigned m = v >> 2;
        int n = (tid + j * 1024) * 4 + e;
        if (off < CAP)
          candArr[off] = (((ull)m) << 16) | (((ull)lc) << 14) | (unsigned)n;
        off++;
        if ((posMask >> bit) & 1u) {
          if (poff < CAP)
            posArr[poff] = (((ull)m) << 14) | (unsigned)(NN - 1 - n);
          poff++;
        }
      }
    }
  }
  __syncthreads();
  const int C = (s_cnt < CAP) ? s_cnt : CAP;
  const int C8 = (C + 7) & ~7;
  const int P = (s_pcnt < CAP) ? s_pcnt : CAP;
  const int P8 = (P + 7) & ~7;

  if (tid < P8 - P) posArr[P + tid] = 0ull;     // pad for unrolled scan
  __syncthreads();

  // ---- exact keys: cat via exact top-NFG positive rank; prio = rn(cat+r) ----
  if (tid < C8 - C) skey[C + tid] = 0ull;       // pad for unrolled rank
  for (int i = tid; i < C; i += 1024) {
    ull rec = candArr[i];
    unsigned m = (unsigned)(rec >> 16);
    unsigned lc = (unsigned)(rec >> 14) & 3u;
    int n = (int)(rec & 0x3FFFull);
    float cat;
    if (lc == 1u) {
      bool sel = true;
      if (needPosRank) {
        ull pkey = (((ull)m) << 14) | (unsigned)(NN - 1 - n);
        sel = (countGreater8(posArr, P8, pkey) < NFG);
      }
      cat = sel ? 3.0f : 1.0f;
    } else {
      cat = (lc == 2u) ? 2.0f : 0.0f;
    }
    float r = __fmul_rn((float)(int)m, 1.1920928955078125e-7f);  // m*2^-23 exact
    float prio = __fadd_rn(cat, r);
    skey[i] = (((ull)__float_as_uint(prio)) << 32) | (unsigned)(NN - 1 - n);
  }
  __syncthreads();

  // ---- rank-by-count (keys distinct); rank<256 == lax.top_k order ----
  for (int i = tid; i < C; i += 1024) {
    ull k = skey[i];
    int rank = countGreater8(skey, C8, k);
    if (rank < NS) {
      ull rec = candArr[i];
      unsigned lc = (unsigned)(rec >> 14) & 3u;
      int n = (int)(rec & 0x3FFFull);
      int bl = (lc == 1u) ? 1 : 0;
      float4 p = reinterpret_cast<const float4*>(prop)[b * NN + n];
      float ap = __fmul_rn(__fsub_rn(p.z, p.x), __fsub_rn(p.w, p.y));

      // exact first-max argmax over 128 gt (bit-identical to reference)
      float best = 0.0f;
      int gi = 0;
#pragma unroll 4
      for (int g = 0; g < GG; ++g) {
        float iou = iou_one(p, ap, sgt[g], sag[g]);
        if (iou > best) { best = iou; gi = g; }
      }
      float4 q = sgt[gi];

      float rcx = __fmul_rn(__fadd_rn(p.x, p.z), 0.5f);
      float rcy = __fmul_rn(__fadd_rn(p.y, p.w), 0.5f);
      float rw  = __fsub_rn(p.z, p.x);
      float rh  = __fsub_rn(p.w, p.y);
      float gcx = __fmul_rn(__fadd_rn(q.x, q.z), 0.5f);
      float gcy = __fmul_rn(__fadd_rn(q.y, q.w), 0.5f);
      float gw  = __fsub_rn(q.z, q.x);
      float gh  = __fsub_rn(q.w, q.y);
      float dx = __fdiv_rn(__fsub_rn(gcx, rcx), rw);
      float dy = __fdiv_rn(__fsub_rn(gcy, rcy), rh);
      float dw = logf(__fdiv_rn(gw, rw));
      float dh = logf(__fdiv_rn(gh, rh));

      const int base = b * NS + rank;
      float4* roi4  = reinterpret_cast<float4*>(out);
      float*  labo  = out + BB * NS * 4;
      float4* tgt4  = reinterpret_cast<float4*>(out + BB * NS * 5);
      float4* inw4  = reinterpret_cast<float4*>(out + BB * NS * 9);
      float4* outw4 = reinterpret_cast<float4*>(out + BB * NS * 13);

      float w = bl ? 1.0f : 0.0f;
      roi4[base]  = p;
      labo[base]  = (float)bl;
      tgt4[base]  = make_float4(dx, dy, dw, dh);
      inw4[base]  = make_float4(w, w, w, w);
      outw4[base] = make_float4(w, w, w, w);
    }
  }
}

extern "C" void kernel_launch(void* const* d_in, const int* in_sizes, int n_in,
                              void* d_out, int out_size) {
  const float* prop = (const float*)d_in[0];  // (16,16384,4) f32
  const float* gt   = (const float*)d_in[1];  // (16,128,4)   f32
  float* out = (float*)d_out;

  ptl_stage1<<<dim3(NN / 512, BB), 256>>>(prop, gt);
  ptl_stage2<<<BB, 1024>>>(prop, gt, out);
}